// round 1
// baseline (speedup 1.0000x reference)
#include <cuda_runtime.h>
#include <math.h>

// ---------------------------------------------------------------------------
// mLSTMBlock: fp32 baseline.
//   B=4096, IN=2048, HID=PROJ=4096, H=8, BH=BI=512, conv K=4
// Pipeline:
//   ln -> [upL, upR gemm] -> conv+silu -> [skip, q,k,v(blockdiag), wi, wf, wo gemm]
//      -> gates (+row reduction) -> groupnorm-fuse -> down gemm (+residual)
// Outputs concatenated: out(B*IN), h(B*HID), c, n, m
// ---------------------------------------------------------------------------

#define BSZ  4096
#define INF  2048
#define HIDF 4096
#define PROJ 4096
#define NH   8
#define BHD  512
#define KCONV 4

// ---- scratch (device globals; no allocation APIs used) ----
__device__ float g_xn   [(size_t)BSZ * INF ];
__device__ float g_xl   [(size_t)BSZ * PROJ];
__device__ float g_xr   [(size_t)BSZ * HIDF];
__device__ float g_xc   [(size_t)BSZ * PROJ];
__device__ float g_xskip[(size_t)BSZ * HIDF];
__device__ float g_q    [(size_t)BSZ * HIDF];
__device__ float g_k    [(size_t)BSZ * HIDF];
__device__ float g_v    [(size_t)BSZ * HIDF];
__device__ float g_it   [(size_t)BSZ * HIDF];
__device__ float g_ft   [(size_t)BSZ * HIDF];
__device__ float g_o    [(size_t)BSZ * HIDF];
__device__ float g_y    [(size_t)BSZ * HIDF];

// ---------------------------------------------------------------------------
// LayerNorm over last dim (IN=2048). One block per row.
// ---------------------------------------------------------------------------
__global__ void ln_kernel(const float* __restrict__ x,
                          const float* __restrict__ w,
                          const float* __restrict__ b,
                          float* __restrict__ out)
{
    const int row = blockIdx.x;
    const float* xr = x + (size_t)row * INF;
    float* op = out + (size_t)row * INF;

    float s = 0.f, s2 = 0.f;
    for (int i = threadIdx.x; i < INF; i += blockDim.x) {
        float v = xr[i];
        s += v; s2 += v * v;
    }
    __shared__ float sh[64];
    #pragma unroll
    for (int off = 16; off; off >>= 1) {
        s  += __shfl_down_sync(0xffffffffu, s,  off);
        s2 += __shfl_down_sync(0xffffffffu, s2, off);
    }
    int warp = threadIdx.x >> 5, lane = threadIdx.x & 31;
    if (lane == 0) { sh[warp] = s; sh[warp + 32] = s2; }
    __syncthreads();
    if (warp == 0) {
        int nw = blockDim.x >> 5;
        s  = (lane < nw) ? sh[lane]      : 0.f;
        s2 = (lane < nw) ? sh[lane + 32] : 0.f;
        #pragma unroll
        for (int off = 16; off; off >>= 1) {
            s  += __shfl_down_sync(0xffffffffu, s,  off);
            s2 += __shfl_down_sync(0xffffffffu, s2, off);
        }
        if (lane == 0) { sh[0] = s; sh[1] = s2; }
    }
    __syncthreads();
    float mu  = sh[0] * (1.f / INF);
    float var = sh[1] * (1.f / INF) - mu * mu;
    float rs  = rsqrtf(var + 1e-5f);
    for (int i = threadIdx.x; i < INF; i += blockDim.x)
        op[i] = (xr[i] - mu) * rs * w[i] + b[i];
}

// ---------------------------------------------------------------------------
// Causal conv (K=4, along feature dim) + SiLU
// ---------------------------------------------------------------------------
__global__ void conv_silu_kernel(const float* __restrict__ xl,
                                 const float* __restrict__ cw,
                                 const float* __restrict__ cb,
                                 float* __restrict__ xc)
{
    size_t idx = (size_t)blockIdx.x * blockDim.x + threadIdx.x;
    if (idx >= (size_t)BSZ * PROJ) return;
    int l = (int)(idx % PROJ);
    size_t rowb = idx - l;
    float acc = cb[0];
    #pragma unroll
    for (int k = 0; k < KCONV; k++) {
        int j = l + k - (KCONV - 1);
        if (j >= 0) acc += cw[k] * xl[rowb + j];
    }
    // silu
    xc[idx] = acc / (1.f + expf(-acc));
}

// ---------------------------------------------------------------------------
// Generic tiled SGEMM: C[z] = epi( (A[z] @ B[z] + bias[z]) * alpha )
//   A: M x K (lda), row-major; B: K x N (ldb), row-major; C: M x N (ldc)
//   batching (for blockdiag): pointer offsets per blockIdx.z
//   epi: 0 = none, 1 = sigmoid, 2 = add resid[row*ldc+col]
//   All tile dims divide exactly (M%128==0, N%128==0, K%8==0) -> no bounds.
// ---------------------------------------------------------------------------
__global__ void __launch_bounds__(256)
gemm_bias_kernel(const float* __restrict__ A, const float* __restrict__ Bm,
                 const float* __restrict__ bias, const float* __restrict__ resid,
                 float* __restrict__ C,
                 int K, int lda, int ldb, int ldc,
                 int aOff, int bOff, int cOff,
                 float alpha, int epi)
{
    const int BM = 128, BN = 128, BK = 8;
    const int z = blockIdx.z;
    A    += (size_t)z * aOff;
    Bm   += (size_t)z * bOff;
    C    += (size_t)z * cOff;
    bias += (size_t)z * cOff;

    __shared__ float As[BK][BM];
    __shared__ float Bs[BK][BN];

    const int tid  = threadIdx.x;
    const int cRow = blockIdx.y;
    const int cCol = blockIdx.x;

    const int innerRowA = tid >> 1;            // 0..127
    const int innerColA = (tid & 1) * 4;       // 0 or 4
    const int innerRowB = tid >> 5;            // 0..7
    const int innerColB = (tid & 31) * 4;      // 0..124

    const float* Ablk = A + (size_t)(cRow * BM) * lda;
    const float* Bblk = Bm + cCol * BN;

    const int tr = (tid >> 4) * 8;             // thread row 0..120
    const int tc = (tid & 15) * 8;             // thread col 0..120

    float acc[8][8];
    #pragma unroll
    for (int i = 0; i < 8; i++)
        #pragma unroll
        for (int j = 0; j < 8; j++) acc[i][j] = 0.f;

    for (int k0 = 0; k0 < K; k0 += BK) {
        float4 a4 = *reinterpret_cast<const float4*>(
            &Ablk[(size_t)innerRowA * lda + k0 + innerColA]);
        As[innerColA + 0][innerRowA] = a4.x;
        As[innerColA + 1][innerRowA] = a4.y;
        As[innerColA + 2][innerRowA] = a4.z;
        As[innerColA + 3][innerRowA] = a4.w;

        float4 b4 = *reinterpret_cast<const float4*>(
            &Bblk[(size_t)(k0 + innerRowB) * ldb + innerColB]);
        *reinterpret_cast<float4*>(&Bs[innerRowB][innerColB]) = b4;

        __syncthreads();
        #pragma unroll
        for (int kk = 0; kk < BK; kk++) {
            float ra[8], rb[8];
            #pragma unroll
            for (int i = 0; i < 8; i++) ra[i] = As[kk][tr + i];
            #pragma unroll
            for (int j = 0; j < 8; j++) rb[j] = Bs[kk][tc + j];
            #pragma unroll
            for (int i = 0; i < 8; i++)
                #pragma unroll
                for (int j = 0; j < 8; j++)
                    acc[i][j] += ra[i] * rb[j];
        }
        __syncthreads();
    }

    const int rowBase = cRow * BM + tr;
    const int colBase = cCol * BN + tc;
    #pragma unroll
    for (int i = 0; i < 8; i++) {
        size_t rbase = (size_t)(rowBase + i) * ldc;
        #pragma unroll
        for (int j = 0; j < 8; j++) {
            int c = colBase + j;
            float v = (acc[i][j] + bias[c]) * alpha;
            if (epi == 1) v = 1.f / (1.f + expf(-v));
            else if (epi == 2) v += resid[rbase + c];
            C[rbase + c] = v;
        }
    }
}

// ---------------------------------------------------------------------------
// mLSTM gate math + full-row (HID) reduction for denom.
// One block (512 threads) per batch row; 8 elements per thread.
// ---------------------------------------------------------------------------
__global__ void __launch_bounds__(512)
gates_kernel(const float* __restrict__ it_, const float* __restrict__ ft_,
             const float* __restrict__ o_,  const float* __restrict__ q_,
             const float* __restrict__ k_,  const float* __restrict__ v_,
             const float* __restrict__ cprev, const float* __restrict__ nprev,
             const float* __restrict__ mprev,
             float* __restrict__ h_out, float* __restrict__ c_out,
             float* __restrict__ n_out, float* __restrict__ m_out)
{
    const int row = blockIdx.x;
    const size_t base = (size_t)row * HIDF;

    float cte[8], qe[8], oe[8];
    float ssum = 0.f;
    #pragma unroll
    for (int r = 0; r < 8; r++) {
        int col = threadIdx.x + r * 512;
        size_t idx = base + col;
        float itv = it_[idx], ftv = ft_[idx], mp = mprev[idx];
        float mt = fmaxf(ftv + mp, itv);
        float iv = expf(itv - mt);
        float fv = expf(ftv + mp - mt);
        float kv = k_[idx];
        float ct = fv * cprev[idx] + iv * (v_[idx] * kv);
        float nt = fv * nprev[idx] + iv * kv;
        float qv = q_[idx];
        m_out[idx] = mt;
        c_out[idx] = ct;
        n_out[idx] = nt;
        float s = nt * qv;
        ssum += s * s;
        cte[r] = ct; qe[r] = qv; oe[r] = o_[idx];
    }

    __shared__ float red[16];
    float s = ssum;
    #pragma unroll
    for (int off = 16; off; off >>= 1)
        s += __shfl_down_sync(0xffffffffu, s, off);
    int warp = threadIdx.x >> 5, lane = threadIdx.x & 31;
    if (lane == 0) red[warp] = s;
    __syncthreads();
    if (warp == 0) {
        s = (lane < 16) ? red[lane] : 0.f;
        #pragma unroll
        for (int off = 8; off; off >>= 1)
            s += __shfl_down_sync(0xffffffffu, s, off);
        if (lane == 0) red[0] = s;
    }
    __syncthreads();
    float inv_denom = 1.f / (sqrtf(red[0]) + 1e-6f);

    #pragma unroll
    for (int r = 0; r < 8; r++) {
        int col = threadIdx.x + r * 512;
        h_out[base + col] = oe[r] * cte[r] * qe[r] * inv_denom;
    }
}

// ---------------------------------------------------------------------------
// GroupNorm(h) * gn_w + gn_b + x_skip, then * silu(x_right) -> y
// One block per (batch row, head); 128 threads, 4 elems each (BH=512).
// ---------------------------------------------------------------------------
__global__ void __launch_bounds__(128)
gn_fuse_kernel(const float* __restrict__ h, const float* __restrict__ gw,
               const float* __restrict__ gb, const float* __restrict__ xskip,
               const float* __restrict__ xr, float* __restrict__ y)
{
    const int b  = blockIdx.x;
    const int hh = blockIdx.y;
    const size_t rowb = (size_t)b * HIDF;
    const size_t base = rowb + hh * BHD;

    float vals[4];
    float s = 0.f, s2 = 0.f;
    #pragma unroll
    for (int r = 0; r < 4; r++) {
        int c = threadIdx.x + r * 128;
        float v = h[base + c];
        vals[r] = v;
        s += v; s2 += v * v;
    }
    __shared__ float red[8];
    #pragma unroll
    for (int off = 16; off; off >>= 1) {
        s  += __shfl_down_sync(0xffffffffu, s,  off);
        s2 += __shfl_down_sync(0xffffffffu, s2, off);
    }
    int warp = threadIdx.x >> 5, lane = threadIdx.x & 31;
    if (lane == 0) { red[warp] = s; red[warp + 4] = s2; }
    __syncthreads();
    if (threadIdx.x == 0) {
        float a = red[0] + red[1] + red[2] + red[3];
        float a2 = red[4] + red[5] + red[6] + red[7];
        red[0] = a; red[4] = a2;
    }
    __syncthreads();
    float mu  = red[0] * (1.f / BHD);
    float var = red[4] * (1.f / BHD) - mu * mu;
    float rs  = rsqrtf(var + 1e-5f);

    #pragma unroll
    for (int r = 0; r < 4; r++) {
        int c = threadIdx.x + r * 128;
        int col = hh * BHD + c;
        float g = (vals[r] - mu) * rs * gw[col] + gb[col] + xskip[rowb + col];
        float xv = xr[rowb + col];
        float sil = xv / (1.f + expf(-xv));
        y[rowb + col] = g * sil;
    }
}

// ---------------------------------------------------------------------------
// Launcher
// ---------------------------------------------------------------------------
extern "C" void kernel_launch(void* const* d_in, const int* in_sizes, int n_in,
                              void* d_out, int out_size)
{
    const float* x      = (const float*)d_in[0];
    // d_in[1] = h_prev (unused by the reference math)
    const float* c_prev = (const float*)d_in[2];
    const float* n_prev = (const float*)d_in[3];
    const float* m_prev = (const float*)d_in[4];
    const float* ln_w   = (const float*)d_in[5];
    const float* ln_b   = (const float*)d_in[6];
    const float* upL_w  = (const float*)d_in[7];
    const float* upL_b  = (const float*)d_in[8];
    const float* upR_w  = (const float*)d_in[9];
    const float* upR_b  = (const float*)d_in[10];
    const float* skip_w = (const float*)d_in[11];
    const float* skip_b = (const float*)d_in[12];
    const float* down_w = (const float*)d_in[13];
    const float* down_b = (const float*)d_in[14];
    const float* conv_w = (const float*)d_in[15];
    const float* conv_b = (const float*)d_in[16];
    const float* wq_w   = (const float*)d_in[17];
    const float* wq_b   = (const float*)d_in[18];
    const float* wk_w   = (const float*)d_in[19];
    const float* wk_b   = (const float*)d_in[20];
    const float* wv_w   = (const float*)d_in[21];
    const float* wv_b   = (const float*)d_in[22];
    const float* wi_w   = (const float*)d_in[23];
    const float* wi_b   = (const float*)d_in[24];
    const float* wf_w   = (const float*)d_in[25];
    const float* wf_b   = (const float*)d_in[26];
    const float* wo_w   = (const float*)d_in[27];
    const float* wo_b   = (const float*)d_in[28];
    const float* gn_w   = (const float*)d_in[29];
    const float* gn_b   = (const float*)d_in[30];

    float *xn, *xl, *xr, *xc, *xskip, *q, *k, *v, *it, *ft, *o, *y;
    cudaGetSymbolAddress((void**)&xn,    g_xn);
    cudaGetSymbolAddress((void**)&xl,    g_xl);
    cudaGetSymbolAddress((void**)&xr,    g_xr);
    cudaGetSymbolAddress((void**)&xc,    g_xc);
    cudaGetSymbolAddress((void**)&xskip, g_xskip);
    cudaGetSymbolAddress((void**)&q,     g_q);
    cudaGetSymbolAddress((void**)&k,     g_k);
    cudaGetSymbolAddress((void**)&v,     g_v);
    cudaGetSymbolAddress((void**)&it,    g_it);
    cudaGetSymbolAddress((void**)&ft,    g_ft);
    cudaGetSymbolAddress((void**)&o,     g_o);
    cudaGetSymbolAddress((void**)&y,     g_y);

    float* outp  = (float*)d_out;
    float* h_out = outp  + (size_t)BSZ * INF;
    float* c_out = h_out + (size_t)BSZ * HIDF;
    float* n_out = c_out + (size_t)BSZ * HIDF;
    float* m_out = n_out + (size_t)BSZ * HIDF;

    const float kscale = (float)(1.0 / sqrt((double)BHD));

    // 1) LayerNorm
    ln_kernel<<<BSZ, 256>>>(x, ln_w, ln_b, xn);

    // 2) x_left = xn @ upL_w + b ; x_right = xn @ upR_w + b
    {
        dim3 g(PROJ / 128, BSZ / 128, 1);
        gemm_bias_kernel<<<g, 256>>>(xn, upL_w, upL_b, nullptr, xl,
                                     INF, INF, PROJ, PROJ, 0, 0, 0, 1.f, 0);
        dim3 g2(HIDF / 128, BSZ / 128, 1);
        gemm_bias_kernel<<<g2, 256>>>(xn, upR_w, upR_b, nullptr, xr,
                                      INF, INF, HIDF, HIDF, 0, 0, 0, 1.f, 0);
    }

    // 3) x_conv = silu(causal_conv(x_left))
    {
        size_t n = (size_t)BSZ * PROJ;
        conv_silu_kernel<<<(unsigned)((n + 255) / 256), 256>>>(xl, conv_w, conv_b, xc);
    }

    // 4) big GEMMs from x_conv / x_left
    {
        dim3 g(HIDF / 128, BSZ / 128, 1);
        // x_skip = xc @ skip_w + b
        gemm_bias_kernel<<<g, 256>>>(xc, skip_w, skip_b, nullptr, xskip,
                                     PROJ, PROJ, HIDF, HIDF, 0, 0, 0, 1.f, 0);
        // i_tilde, f_tilde
        gemm_bias_kernel<<<g, 256>>>(xc, wi_w, wi_b, nullptr, it,
                                     PROJ, PROJ, HIDF, HIDF, 0, 0, 0, 1.f, 0);
        gemm_bias_kernel<<<g, 256>>>(xc, wf_w, wf_b, nullptr, ft,
                                     PROJ, PROJ, HIDF, HIDF, 0, 0, 0, 1.f, 0);
        // o = sigmoid(x_left @ wo_w + b)
        gemm_bias_kernel<<<g, 256>>>(xl, wo_w, wo_b, nullptr, o,
                                     PROJ, PROJ, HIDF, HIDF, 0, 0, 0, 1.f, 1);
    }

    // 5) blockdiag q, k, v  (grid.z = head)
    {
        dim3 g(BHD / 128, BSZ / 128, NH);
        gemm_bias_kernel<<<g, 256>>>(xc, wq_w, wq_b, nullptr, q,
                                     BHD, PROJ, BHD, HIDF,
                                     BHD, BHD * BHD, BHD, 1.f, 0);
        gemm_bias_kernel<<<g, 256>>>(xc, wk_w, wk_b, nullptr, k,
                                     BHD, PROJ, BHD, HIDF,
                                     BHD, BHD * BHD, BHD, kscale, 0);
        gemm_bias_kernel<<<g, 256>>>(xl, wv_w, wv_b, nullptr, v,
                                     BHD, PROJ, BHD, HIDF,
                                     BHD, BHD * BHD, BHD, 1.f, 0);
    }

    // 6) mLSTM gates + h_t (writes h,c,n,m directly into d_out)
    gates_kernel<<<BSZ, 512>>>(it, ft, o, q, k, v, c_prev, n_prev, m_prev,
                               h_out, c_out, n_out, m_out);

    // 7) groupnorm + skip + silu(x_right) gate -> y
    {
        dim3 g(BSZ, NH, 1);
        gn_fuse_kernel<<<g, 128>>>(h_out, gn_w, gn_b, xskip, xr, y);
    }

    // 8) out = y @ down_w + down_b + x
    {
        dim3 g(INF / 128, BSZ / 128, 1);
        gemm_bias_kernel<<<g, 256>>>(y, down_w, down_b, x, outp,
                                     HIDF, HIDF, INF, INF, 0, 0, 0, 1.f, 2);
    }
}

// round 3
// speedup vs baseline: 3.6682x; 3.6682x over previous
#include <cuda_runtime.h>
#include <math.h>

// ---------------------------------------------------------------------------
// mLSTMBlock: TF32 tensor-core GEMMs + fused elementwise.
//   B=4096, IN=2048, HID=PROJ=4096, H=8, BH=BI=512, conv K=4
// ---------------------------------------------------------------------------

#define BSZ  4096
#define INF  2048
#define HIDF 4096
#define PROJ 4096
#define NH   8
#define BHD  512
#define KCONV 4

// ---- scratch (device globals; no allocation APIs used) ----
__device__ float g_xn   [(size_t)BSZ * INF ];
__device__ float g_xl   [(size_t)BSZ * PROJ];
__device__ float g_xr   [(size_t)BSZ * HIDF];
__device__ float g_xc   [(size_t)BSZ * PROJ];
__device__ float g_xskip[(size_t)BSZ * HIDF];
__device__ float g_q    [(size_t)BSZ * HIDF];
__device__ float g_k    [(size_t)BSZ * HIDF];
__device__ float g_v    [(size_t)BSZ * HIDF];
__device__ float g_it   [(size_t)BSZ * HIDF];
__device__ float g_ft   [(size_t)BSZ * HIDF];
__device__ float g_o    [(size_t)BSZ * HIDF];
__device__ float g_y    [(size_t)BSZ * HIDF];

// ---------------------------------------------------------------------------
// helpers
// ---------------------------------------------------------------------------
__device__ __forceinline__ unsigned smem_u32(const void* p) {
    return (unsigned)__cvta_generic_to_shared(p);
}
__device__ __forceinline__ void cp16(unsigned dst, const float* src) {
    asm volatile("cp.async.cg.shared.global [%0], [%1], 16;\n" :: "r"(dst), "l"(src));
}
__device__ __forceinline__ unsigned f2tf32(float x) {
    unsigned u;
    asm("cvt.rna.tf32.f32 %0, %1;" : "=r"(u) : "f"(x));
    return u;
}

// ---------------------------------------------------------------------------
// LayerNorm over last dim (IN=2048). One block per row.
// ---------------------------------------------------------------------------
__global__ void ln_kernel(const float* __restrict__ x,
                          const float* __restrict__ w,
                          const float* __restrict__ b,
                          float* __restrict__ out)
{
    const int row = blockIdx.x;
    const float* xr = x + (size_t)row * INF;
    float* op = out + (size_t)row * INF;

    float s = 0.f, s2 = 0.f;
    for (int i = threadIdx.x; i < INF; i += blockDim.x) {
        float v = xr[i];
        s += v; s2 += v * v;
    }
    __shared__ float sh[64];
    #pragma unroll
    for (int off = 16; off; off >>= 1) {
        s  += __shfl_down_sync(0xffffffffu, s,  off);
        s2 += __shfl_down_sync(0xffffffffu, s2, off);
    }
    int warp = threadIdx.x >> 5, lane = threadIdx.x & 31;
    if (lane == 0) { sh[warp] = s; sh[warp + 32] = s2; }
    __syncthreads();
    if (warp == 0) {
        int nw = blockDim.x >> 5;
        s  = (lane < nw) ? sh[lane]      : 0.f;
        s2 = (lane < nw) ? sh[lane + 32] : 0.f;
        #pragma unroll
        for (int off = 16; off; off >>= 1) {
            s  += __shfl_down_sync(0xffffffffu, s,  off);
            s2 += __shfl_down_sync(0xffffffffu, s2, off);
        }
        if (lane == 0) { sh[0] = s; sh[1] = s2; }
    }
    __syncthreads();
    float mu  = sh[0] * (1.f / INF);
    float var = sh[1] * (1.f / INF) - mu * mu;
    float rs  = rsqrtf(var + 1e-5f);
    for (int i = threadIdx.x; i < INF; i += blockDim.x)
        op[i] = (xr[i] - mu) * rs * w[i] + b[i];
}

// ---------------------------------------------------------------------------
// Causal conv (K=4, along feature dim) + SiLU
// ---------------------------------------------------------------------------
__global__ void conv_silu_kernel(const float* __restrict__ xl,
                                 const float* __restrict__ cw,
                                 const float* __restrict__ cb,
                                 float* __restrict__ xc)
{
    size_t idx = (size_t)blockIdx.x * blockDim.x + threadIdx.x;
    if (idx >= (size_t)BSZ * PROJ) return;
    int l = (int)(idx % PROJ);
    size_t rowb = idx - l;
    float acc = cb[0];
    #pragma unroll
    for (int k = 0; k < KCONV; k++) {
        int j = l + k - (KCONV - 1);
        if (j >= 0) acc += cw[k] * xl[rowb + j];
    }
    xc[idx] = acc / (1.f + expf(-acc));
}

// ---------------------------------------------------------------------------
// TF32 tensor-core GEMM: C[z] = epi( (A[z] @ B[z] + bias[z]) * alpha )
//   128x128 tile, BK=16, 256 threads (8 warps, 64x32 warp tiles),
//   cp.async 2-stage double buffer. All dims divide tiles exactly.
//   epi: 0 none, 1 sigmoid, 2 add resid[row*ldc+col]
// ---------------------------------------------------------------------------
#define ASTRIDE 20
#define BSTRIDE 136

__global__ void __launch_bounds__(256)
gemm_tf32_kernel(const float* __restrict__ A, const float* __restrict__ Bm,
                 const float* __restrict__ bias, const float* __restrict__ resid,
                 float* __restrict__ C,
                 int K, int lda, int ldb, int ldc,
                 int aOff, int bOff, int cOff,
                 float alpha, int epi)
{
    const int z = blockIdx.z;
    A    += (size_t)z * aOff;
    Bm   += (size_t)z * bOff;
    C    += (size_t)z * cOff;
    bias += (size_t)z * cOff;

    __shared__ float As[2][128 * ASTRIDE];   // [m][k], stride 20
    __shared__ float Bs[2][16 * BSTRIDE];    // [k][n], stride 136

    const int tid  = threadIdx.x;
    const int lane = tid & 31;
    const int warp = tid >> 5;
    const int g    = lane >> 2;      // 0..7
    const int tig  = lane & 3;       // 0..3
    const int wr   = warp >> 2;      // 0..1
    const int wc   = warp & 3;       // 0..3
    const int mBase = wr * 64;
    const int nBase = wc * 32;

    const float* Ablk = A + (size_t)(blockIdx.y * 128) * lda;
    const float* Bblk = Bm + blockIdx.x * 128;

    // loader indices
    const int am = tid >> 2;          // 0..63 (A row, +64 second)
    const int ak = (tid & 3) * 4;     // 0,4,8,12
    const int bk = tid >> 5;          // 0..7 (B k-row, +8 second)
    const int bn = (tid & 31) * 4;    // 0..124

    float acc[4][4][4];
    #pragma unroll
    for (int mt = 0; mt < 4; mt++)
        #pragma unroll
        for (int nt = 0; nt < 4; nt++)
            #pragma unroll
            for (int r = 0; r < 4; r++) acc[mt][nt][r] = 0.f;

    const int KT = K >> 4;

    // prefetch stage 0
    {
        const float* ap = Ablk + (size_t)am * lda + ak;
        cp16(smem_u32(&As[0][am * ASTRIDE + ak]), ap);
        cp16(smem_u32(&As[0][(am + 64) * ASTRIDE + ak]), ap + (size_t)64 * lda);
        const float* bp = Bblk + (size_t)bk * ldb + bn;
        cp16(smem_u32(&Bs[0][bk * BSTRIDE + bn]), bp);
        cp16(smem_u32(&Bs[0][(bk + 8) * BSTRIDE + bn]), bp + (size_t)8 * ldb);
        asm volatile("cp.async.commit_group;\n");
    }

    for (int kt = 0; kt < KT; kt++) {
        asm volatile("cp.async.wait_group 0;\n");
        __syncthreads();

        if (kt + 1 < KT) {
            int s = (kt + 1) & 1;
            int kg = (kt + 1) * 16;
            const float* ap = Ablk + (size_t)am * lda + kg + ak;
            cp16(smem_u32(&As[s][am * ASTRIDE + ak]), ap);
            cp16(smem_u32(&As[s][(am + 64) * ASTRIDE + ak]), ap + (size_t)64 * lda);
            const float* bp = Bblk + (size_t)(kg + bk) * ldb + bn;
            cp16(smem_u32(&Bs[s][bk * BSTRIDE + bn]), bp);
            cp16(smem_u32(&Bs[s][(bk + 8) * BSTRIDE + bn]), bp + (size_t)8 * ldb);
            asm volatile("cp.async.commit_group;\n");
        }

        const float* as = As[kt & 1];
        const float* bs = Bs[kt & 1];

        #pragma unroll
        for (int kp = 0; kp < 2; kp++) {
            const int k0 = kp * 8;
            unsigned af[4][4], bf[4][2];
            #pragma unroll
            for (int mt = 0; mt < 4; mt++) {
                int r = mBase + mt * 16 + g;
                af[mt][0] = f2tf32(as[r * ASTRIDE + k0 + tig]);
                af[mt][1] = f2tf32(as[(r + 8) * ASTRIDE + k0 + tig]);
                af[mt][2] = f2tf32(as[r * ASTRIDE + k0 + tig + 4]);
                af[mt][3] = f2tf32(as[(r + 8) * ASTRIDE + k0 + tig + 4]);
            }
            #pragma unroll
            for (int nt = 0; nt < 4; nt++) {
                int c = nBase + nt * 8 + g;
                bf[nt][0] = f2tf32(bs[(k0 + tig) * BSTRIDE + c]);
                bf[nt][1] = f2tf32(bs[(k0 + tig + 4) * BSTRIDE + c]);
            }
            #pragma unroll
            for (int mt = 0; mt < 4; mt++)
                #pragma unroll
                for (int nt = 0; nt < 4; nt++) {
                    asm volatile(
                        "mma.sync.aligned.m16n8k8.row.col.f32.tf32.tf32.f32 "
                        "{%0,%1,%2,%3}, {%4,%5,%6,%7}, {%8,%9}, {%0,%1,%2,%3};"
                        : "+f"(acc[mt][nt][0]), "+f"(acc[mt][nt][1]),
                          "+f"(acc[mt][nt][2]), "+f"(acc[mt][nt][3])
                        : "r"(af[mt][0]), "r"(af[mt][1]),
                          "r"(af[mt][2]), "r"(af[mt][3]),
                          "r"(bf[nt][0]), "r"(bf[nt][1]));
                }
        }
        __syncthreads();
    }

    // epilogue
    const int rowBlk = blockIdx.y * 128;
    const int colBlk = blockIdx.x * 128;
    #pragma unroll
    for (int mt = 0; mt < 4; mt++) {
        int r0 = rowBlk + mBase + mt * 16 + g;
        #pragma unroll
        for (int nt = 0; nt < 4; nt++) {
            int c0 = colBlk + nBase + nt * 8 + tig * 2;
            float b0 = bias[c0], b1 = bias[c0 + 1];
            #pragma unroll
            for (int hi = 0; hi < 2; hi++) {
                int rr = r0 + hi * 8;
                size_t rb = (size_t)rr * ldc;
                float v0 = (acc[mt][nt][hi * 2 + 0] + b0) * alpha;
                float v1 = (acc[mt][nt][hi * 2 + 1] + b1) * alpha;
                if (epi == 1) {
                    v0 = 1.f / (1.f + expf(-v0));
                    v1 = 1.f / (1.f + expf(-v1));
                } else if (epi == 2) {
                    v0 += resid[rb + c0];
                    v1 += resid[rb + c0 + 1];
                }
                float2 vv = make_float2(v0, v1);
                *reinterpret_cast<float2*>(&C[rb + c0]) = vv;
            }
        }
    }
}

// ---------------------------------------------------------------------------
// mLSTM gate math + full-row (HID) reduction for denom.
// ---------------------------------------------------------------------------
__global__ void __launch_bounds__(512)
gates_kernel(const float* __restrict__ it_, const float* __restrict__ ft_,
             const float* __restrict__ o_,  const float* __restrict__ q_,
             const float* __restrict__ k_,  const float* __restrict__ v_,
             const float* __restrict__ cprev, const float* __restrict__ nprev,
             const float* __restrict__ mprev,
             float* __restrict__ h_out, float* __restrict__ c_out,
             float* __restrict__ n_out, float* __restrict__ m_out)
{
    const int row = blockIdx.x;
    const size_t base = (size_t)row * HIDF;

    float cte[8], qe[8], oe[8];
    float ssum = 0.f;
    #pragma unroll
    for (int r = 0; r < 8; r++) {
        int col = threadIdx.x + r * 512;
        size_t idx = base + col;
        float itv = it_[idx], ftv = ft_[idx], mp = mprev[idx];
        float mt = fmaxf(ftv + mp, itv);
        float iv = expf(itv - mt);
        float fv = expf(ftv + mp - mt);
        float kv = k_[idx];
        float ct = fv * cprev[idx] + iv * (v_[idx] * kv);
        float nt = fv * nprev[idx] + iv * kv;
        float qv = q_[idx];
        m_out[idx] = mt;
        c_out[idx] = ct;
        n_out[idx] = nt;
        float s = nt * qv;
        ssum += s * s;
        cte[r] = ct; qe[r] = qv; oe[r] = o_[idx];
    }

    __shared__ float red[16];
    float s = ssum;
    #pragma unroll
    for (int off = 16; off; off >>= 1)
        s += __shfl_down_sync(0xffffffffu, s, off);
    int warp = threadIdx.x >> 5, lane = threadIdx.x & 31;
    if (lane == 0) red[warp] = s;
    __syncthreads();
    if (warp == 0) {
        s = (lane < 16) ? red[lane] : 0.f;
        #pragma unroll
        for (int off = 8; off; off >>= 1)
            s += __shfl_down_sync(0xffffffffu, s, off);
        if (lane == 0) red[0] = s;
    }
    __syncthreads();
    float inv_denom = 1.f / (sqrtf(red[0]) + 1e-6f);

    #pragma unroll
    for (int r = 0; r < 8; r++) {
        int col = threadIdx.x + r * 512;
        h_out[base + col] = oe[r] * cte[r] * qe[r] * inv_denom;
    }
}

// ---------------------------------------------------------------------------
// GroupNorm(h) * gn_w + gn_b + x_skip, then * silu(x_right) -> y
// ---------------------------------------------------------------------------
__global__ void __launch_bounds__(128)
gn_fuse_kernel(const float* __restrict__ h, const float* __restrict__ gw,
               const float* __restrict__ gb, const float* __restrict__ xskip,
               const float* __restrict__ xr, float* __restrict__ y)
{
    const int b  = blockIdx.x;
    const int hh = blockIdx.y;
    const size_t rowb = (size_t)b * HIDF;
    const size_t base = rowb + hh * BHD;

    float vals[4];
    float s = 0.f, s2 = 0.f;
    #pragma unroll
    for (int r = 0; r < 4; r++) {
        int c = threadIdx.x + r * 128;
        float v = h[base + c];
        vals[r] = v;
        s += v; s2 += v * v;
    }
    __shared__ float red[8];
    #pragma unroll
    for (int off = 16; off; off >>= 1) {
        s  += __shfl_down_sync(0xffffffffu, s,  off);
        s2 += __shfl_down_sync(0xffffffffu, s2, off);
    }
    int warp = threadIdx.x >> 5, lane = threadIdx.x & 31;
    if (lane == 0) { red[warp] = s; red[warp + 4] = s2; }
    __syncthreads();
    if (threadIdx.x == 0) {
        float a = red[0] + red[1] + red[2] + red[3];
        float a2 = red[4] + red[5] + red[6] + red[7];
        red[0] = a; red[4] = a2;
    }
    __syncthreads();
    float mu  = red[0] * (1.f / BHD);
    float var = red[4] * (1.f / BHD) - mu * mu;
    float rs  = rsqrtf(var + 1e-5f);

    #pragma unroll
    for (int r = 0; r < 4; r++) {
        int c = threadIdx.x + r * 128;
        int col = hh * BHD + c;
        float g = (vals[r] - mu) * rs * gw[col] + gb[col] + xskip[rowb + col];
        float xv = xr[rowb + col];
        float sil = xv / (1.f + expf(-xv));
        y[rowb + col] = g * sil;
    }
}

// ---------------------------------------------------------------------------
// Launcher
// ---------------------------------------------------------------------------
extern "C" void kernel_launch(void* const* d_in, const int* in_sizes, int n_in,
                              void* d_out, int out_size)
{
    const float* x      = (const float*)d_in[0];
    const float* c_prev = (const float*)d_in[2];
    const float* n_prev = (const float*)d_in[3];
    const float* m_prev = (const float*)d_in[4];
    const float* ln_w   = (const float*)d_in[5];
    const float* ln_b   = (const float*)d_in[6];
    const float* upL_w  = (const float*)d_in[7];
    const float* upL_b  = (const float*)d_in[8];
    const float* upR_w  = (const float*)d_in[9];
    const float* upR_b  = (const float*)d_in[10];
    const float* skip_w = (const float*)d_in[11];
    const float* skip_b = (const float*)d_in[12];
    const float* down_w = (const float*)d_in[13];
    const float* down_b = (const float*)d_in[14];
    const float* conv_w = (const float*)d_in[15];
    const float* conv_b = (const float*)d_in[16];
    const float* wq_w   = (const float*)d_in[17];
    const float* wq_b   = (const float*)d_in[18];
    const float* wk_w   = (const float*)d_in[19];
    const float* wk_b   = (const float*)d_in[20];
    const float* wv_w   = (const float*)d_in[21];
    const float* wv_b   = (const float*)d_in[22];
    const float* wi_w   = (const float*)d_in[23];
    const float* wi_b   = (const float*)d_in[24];
    const float* wf_w   = (const float*)d_in[25];
    const float* wf_b   = (const float*)d_in[26];
    const float* wo_w   = (const float*)d_in[27];
    const float* wo_b   = (const float*)d_in[28];
    const float* gn_w   = (const float*)d_in[29];
    const float* gn_b   = (const float*)d_in[30];

    float *xn, *xl, *xr, *xc, *xskip, *q, *k, *v, *it, *ft, *o, *y;
    cudaGetSymbolAddress((void**)&xn,    g_xn);
    cudaGetSymbolAddress((void**)&xl,    g_xl);
    cudaGetSymbolAddress((void**)&xr,    g_xr);
    cudaGetSymbolAddress((void**)&xc,    g_xc);
    cudaGetSymbolAddress((void**)&xskip, g_xskip);
    cudaGetSymbolAddress((void**)&q,     g_q);
    cudaGetSymbolAddress((void**)&k,     g_k);
    cudaGetSymbolAddress((void**)&v,     g_v);
    cudaGetSymbolAddress((void**)&it,    g_it);
    cudaGetSymbolAddress((void**)&ft,    g_ft);
    cudaGetSymbolAddress((void**)&o,     g_o);
    cudaGetSymbolAddress((void**)&y,     g_y);

    float* outp  = (float*)d_out;
    float* h_out = outp  + (size_t)BSZ * INF;
    float* c_out = h_out + (size_t)BSZ * HIDF;
    float* n_out = c_out + (size_t)BSZ * HIDF;
    float* m_out = n_out + (size_t)BSZ * HIDF;

    const float kscale = (float)(1.0 / sqrt((double)BHD));

    // 1) LayerNorm
    ln_kernel<<<BSZ, 256>>>(x, ln_w, ln_b, xn);

    // 2) x_left = xn @ upL_w + b ; x_right = xn @ upR_w + b
    {
        dim3 g(PROJ / 128, BSZ / 128, 1);
        gemm_tf32_kernel<<<g, 256>>>(xn, upL_w, upL_b, nullptr, xl,
                                     INF, INF, PROJ, PROJ, 0, 0, 0, 1.f, 0);
        dim3 g2(HIDF / 128, BSZ / 128, 1);
        gemm_tf32_kernel<<<g2, 256>>>(xn, upR_w, upR_b, nullptr, xr,
                                      INF, INF, HIDF, HIDF, 0, 0, 0, 1.f, 0);
    }

    // 3) x_conv = silu(causal_conv(x_left))
    {
        size_t n = (size_t)BSZ * PROJ;
        conv_silu_kernel<<<(unsigned)((n + 255) / 256), 256>>>(xl, conv_w, conv_b, xc);
    }

    // 4) big GEMMs from x_conv / x_left
    {
        dim3 g(HIDF / 128, BSZ / 128, 1);
        gemm_tf32_kernel<<<g, 256>>>(xc, skip_w, skip_b, nullptr, xskip,
                                     PROJ, PROJ, HIDF, HIDF, 0, 0, 0, 1.f, 0);
        gemm_tf32_kernel<<<g, 256>>>(xc, wi_w, wi_b, nullptr, it,
                                     PROJ, PROJ, HIDF, HIDF, 0, 0, 0, 1.f, 0);
        gemm_tf32_kernel<<<g, 256>>>(xc, wf_w, wf_b, nullptr, ft,
                                     PROJ, PROJ, HIDF, HIDF, 0, 0, 0, 1.f, 0);
        gemm_tf32_kernel<<<g, 256>>>(xl, wo_w, wo_b, nullptr, o,
                                     PROJ, PROJ, HIDF, HIDF, 0, 0, 0, 1.f, 1);
    }

    // 5) blockdiag q, k, v  (grid.z = head)
    {
        dim3 g(BHD / 128, BSZ / 128, NH);
        gemm_tf32_kernel<<<g, 256>>>(xc, wq_w, wq_b, nullptr, q,
                                     BHD, PROJ, BHD, HIDF,
                                     BHD, BHD * BHD, BHD, 1.f, 0);
        gemm_tf32_kernel<<<g, 256>>>(xc, wk_w, wk_b, nullptr, k,
                                     BHD, PROJ, BHD, HIDF,
                                     BHD, BHD * BHD, BHD, kscale, 0);
        gemm_tf32_kernel<<<g, 256>>>(xl, wv_w, wv_b, nullptr, v,
                                     BHD, PROJ, BHD, HIDF,
                                     BHD, BHD * BHD, BHD, 1.f, 0);
    }

    // 6) mLSTM gates + h_t
    gates_kernel<<<BSZ, 512>>>(it, ft, o, q, k, v, c_prev, n_prev, m_prev,
                               h_out, c_out, n_out, m_out);

    // 7) groupnorm + skip + silu(x_right) gate -> y
    {
        dim3 g(BSZ, NH, 1);
        gn_fuse_kernel<<<g, 128>>>(h_out, gn_w, gn_b, xskip, xr, y);
    }

    // 8) out = y @ down_w + down_b + x
    {
        dim3 g(INF / 128, BSZ / 128, 1);
        gemm_tf32_kernel<<<g, 256>>>(y, down_w, down_b, x, outp,
                                     HIDF, HIDF, INF, INF, 0, 0, 0, 1.f, 2);
    }
}